// round 8
// baseline (speedup 1.0000x reference)
#include <cuda_runtime.h>
#include <cuda_bf16.h>
#include <cstdint>

#define NN   50000
#define EE   400000
#define NH   12
#define HC   32
#define D0   128
#define NHC  (NH*HC)   // 384
#define NC   2

// ---------------- scratch (static device globals) -----------------------------
__device__ float g_xl[(size_t)NN * NHC];       // 76.8 MB (fits L2)
__device__ float g_xr[(size_t)NN * NHC];       // 76.8 MB
__device__ float g_act[(size_t)NN * HC];
__device__ float g_xlo[NN * NC];
__device__ float g_xro[NN * NC];
__device__ int   g_rowptr[NN + 1];
__device__ int   g_cnt[NN];
__device__ int   g_adj[EE];                    // src node ids grouped by dst

// pre-split bf16 operands
__device__ __nv_bfloat16 g_ah[(size_t)NN * D0];        // A hi (K=128 max)
__device__ __nv_bfloat16 g_al[(size_t)NN * D0];        // A lo
__device__ __nv_bfloat16 g_wh[2 * NHC * D0];           // W^T hi, [z][n][k]
__device__ __nv_bfloat16 g_wl[2 * NHC * D0];           // W^T lo

__device__ __forceinline__ float lrelu(float v) { return v > 0.f ? v : 0.2f * v; }

__device__ __forceinline__ uint32_t smem_u32(const void* p) {
    uint32_t a;
    asm("{ .reg .u64 t; cvta.to.shared.u64 t, %1; cvt.u32.u64 %0, t; }" : "=r"(a) : "l"(p));
    return a;
}
__device__ __forceinline__ void ldsm4(uint32_t* r, uint32_t addr) {
    asm volatile("ldmatrix.sync.aligned.m8n8.x4.shared.b16 {%0,%1,%2,%3}, [%4];"
                 : "=r"(r[0]), "=r"(r[1]), "=r"(r[2]), "=r"(r[3]) : "r"(addr));
}
__device__ __forceinline__ void mma_bf16(float* c, const uint32_t* a, uint32_t b0, uint32_t b1) {
    asm volatile(
        "mma.sync.aligned.m16n8k16.row.col.f32.bf16.bf16.f32 "
        "{%0,%1,%2,%3}, {%4,%5,%6,%7}, {%8,%9}, {%0,%1,%2,%3};"
        : "+f"(c[0]), "+f"(c[1]), "+f"(c[2]), "+f"(c[3])
        : "r"(a[0]), "r"(a[1]), "r"(a[2]), "r"(a[3]), "r"(b0), "r"(b1));
}
// L2 cache policies (size-unrestricted via cache_hint form)
__device__ __forceinline__ uint64_t pol_evict_last() {
    uint64_t p;
    asm("createpolicy.fractional.L2::evict_last.b64 %0, 1.0;" : "=l"(p));
    return p;
}
__device__ __forceinline__ uint64_t pol_evict_first() {
    uint64_t p;
    asm("createpolicy.fractional.L2::evict_first.b64 %0, 1.0;" : "=l"(p));
    return p;
}
__device__ __forceinline__ float4 ldg_hint4(const float* p, uint64_t pol) {
    float4 v;
    asm volatile("ld.global.nc.L2::cache_hint.v4.f32 {%0,%1,%2,%3}, [%4], %5;"
                 : "=f"(v.x), "=f"(v.y), "=f"(v.z), "=f"(v.w) : "l"(p), "l"(pol));
    return v;
}

// ---------------- split kernels -------------------------------------------------
template <int K>
__global__ void k_cvtA(const float* __restrict__ A, int M) {
    int i = blockIdx.x * blockDim.x + threadIdx.x;       // float4 index
    if (i >= M * K / 4) return;
    float4 v = reinterpret_cast<const float4*>(A)[i];
    __nv_bfloat162 h01 = __floats2bfloat162_rn(v.x, v.y);
    __nv_bfloat162 h23 = __floats2bfloat162_rn(v.z, v.w);
    float2 f01 = __bfloat1622float2(h01);
    float2 f23 = __bfloat1622float2(h23);
    __nv_bfloat162 l01 = __floats2bfloat162_rn(v.x - f01.x, v.y - f01.y);
    __nv_bfloat162 l23 = __floats2bfloat162_rn(v.z - f23.x, v.w - f23.y);
    uint2 h = make_uint2(*reinterpret_cast<uint32_t*>(&h01), *reinterpret_cast<uint32_t*>(&h23));
    uint2 l = make_uint2(*reinterpret_cast<uint32_t*>(&l01), *reinterpret_cast<uint32_t*>(&l23));
    reinterpret_cast<uint2*>(g_ah)[i] = h;
    reinterpret_cast<uint2*>(g_al)[i] = l;
}

template <int K>
__global__ void k_cvtW(const float* __restrict__ Wa, const float* __restrict__ Wb) {
    int i = blockIdx.x * blockDim.x + threadIdx.x;       // over 2*NHC*K
    if (i >= 2 * NHC * K) return;
    int z = i / (NHC * K);
    int r = i % (NHC * K);
    int n = r / K, k = r % K;
    const float* W = z ? Wb : Wa;
    float v = W[(size_t)k * NHC + n];
    __nv_bfloat16 h = __float2bfloat16(v);
    __nv_bfloat16 l = __float2bfloat16(v - __bfloat162float(h));
    g_wh[(size_t)z * NHC * K + (size_t)n * K + k] = h;
    g_wl[(size_t)z * NHC * K + (size_t)n * K + k] = l;
}

// ---------------- bf16x3 HMMA GEMM: C[M,384] = A[M,K] @ W[K,384] + bias --------
template <int K>
__global__ __launch_bounds__(256, 2)
void k_gemm_mma(const float* __restrict__ bias, float* __restrict__ C,
                const __nv_bfloat16* __restrict__ wh, const __nv_bfloat16* __restrict__ wl,
                int M, int Ncol) {
    constexpr int BM = 128, BN = 64;
    constexpr int ST  = K * 2 + 16;
    constexpr int SZA = BM * ST;
    constexpr int SZB = BN * ST;
    constexpr int KV  = K / 8;

    extern __shared__ char smem[];
    char* sAh = smem;
    char* sAl = smem + SZA;
    char* sBh = smem + 2 * SZA;
    char* sBl = smem + 2 * SZA + SZB;

    const int rowBase = blockIdx.y * BM;
    const int colBase = blockIdx.x * BN;
    const int tid  = threadIdx.x;
    const int wid  = tid >> 5;
    const int lane = tid & 31;
    const int wm   = wid & 3;
    const int wn   = wid >> 2;

    for (int i = tid; i < BM * KV; i += 256) {
        int r  = i / KV;
        int c  = i % KV;
        int gr = rowBase + r;
        uint4 h = make_uint4(0, 0, 0, 0), l = make_uint4(0, 0, 0, 0);
        if (gr < M) {
            h = reinterpret_cast<const uint4*>(g_ah + (size_t)gr * K)[c];
            l = reinterpret_cast<const uint4*>(g_al + (size_t)gr * K)[c];
        }
        *reinterpret_cast<uint4*>(sAh + r * ST + c * 16) = h;
        *reinterpret_cast<uint4*>(sAl + r * ST + c * 16) = l;
    }
    for (int i = tid; i < BN * KV; i += 256) {
        int n = i / KV;
        int c = i % KV;
        *reinterpret_cast<uint4*>(sBh + n * ST + c * 16) =
            reinterpret_cast<const uint4*>(wh + (size_t)(colBase + n) * K)[c];
        *reinterpret_cast<uint4*>(sBl + n * ST + c * 16) =
            reinterpret_cast<const uint4*>(wl + (size_t)(colBase + n) * K)[c];
    }
    __syncthreads();

    const uint32_t sb = smem_u32(smem);
    const int g  = lane >> 3;
    const int ri = lane & 7;

    float acc[2][4][4];
#pragma unroll
    for (int mt = 0; mt < 2; mt++)
#pragma unroll
        for (int nt = 0; nt < 4; nt++)
#pragma unroll
            for (int q = 0; q < 4; q++) acc[mt][nt][q] = 0.f;

#pragma unroll
    for (int kk = 0; kk < K / 16; kk++) {
        uint32_t aH[2][4], aL[2][4], bH[2][4], bL[2][4];
#pragma unroll
        for (int mt = 0; mt < 2; mt++) {
            int row = wm * 32 + mt * 16 + ri + (g & 1) * 8;
            int col = kk * 16 + (g >> 1) * 8;
            uint32_t ad = sb + row * ST + col * 2;
            ldsm4(aH[mt], ad);
            ldsm4(aL[mt], ad + SZA);
        }
#pragma unroll
        for (int p = 0; p < 2; p++) {
            int row = wn * 32 + p * 16 + ri + (g >> 1) * 8;
            int col = kk * 16 + (g & 1) * 8;
            uint32_t bd = sb + 2 * SZA + row * ST + col * 2;
            ldsm4(bH[p], bd);
            ldsm4(bL[p], bd + SZB);
        }
#pragma unroll
        for (int mt = 0; mt < 2; mt++)
#pragma unroll
            for (int nt = 0; nt < 4; nt++) {
                int p = nt >> 1, o = (nt & 1) * 2;
                mma_bf16(acc[mt][nt], aH[mt], bH[p][o], bH[p][o + 1]);
                mma_bf16(acc[mt][nt], aH[mt], bL[p][o], bL[p][o + 1]);
                mma_bf16(acc[mt][nt], aL[mt], bH[p][o], bH[p][o + 1]);
            }
    }

#pragma unroll
    for (int mt = 0; mt < 2; mt++) {
#pragma unroll
        for (int nt = 0; nt < 4; nt++) {
            int gr = rowBase + wm * 32 + mt * 16 + (lane >> 2);
            int gc = colBase + wn * 32 + nt * 8 + (lane & 3) * 2;
            float b0 = bias[gc], b1 = bias[gc + 1];
            if (gr < M) {
                float2 o = make_float2(acc[mt][nt][0] + b0, acc[mt][nt][1] + b1);
                *reinterpret_cast<float2*>(&C[(size_t)gr * Ncol + gc]) = o;
            }
            if (gr + 8 < M) {
                float2 o = make_float2(acc[mt][nt][2] + b0, acc[mt][nt][3] + b1);
                *reinterpret_cast<float2*>(&C[(size_t)(gr + 8) * Ncol + gc]) = o;
            }
        }
    }
}

// ---------------- CSR build ----------------------------------------------------
__global__ void k_count(const int* __restrict__ dst, int* cnt) {
    int i = blockIdx.x * blockDim.x + threadIdx.x;
    if (i < EE) atomicAdd(&cnt[dst[i]], 1);
}

__global__ void k_scan(const int* __restrict__ cnt, int* __restrict__ rowptr) {
    __shared__ int wsum[32];
    __shared__ int carry;
    int lane = threadIdx.x & 31, wid = threadIdx.x >> 5;
    if (threadIdx.x == 0) { carry = 0; rowptr[0] = 0; }
    __syncthreads();
    for (int base = 0; base < NN; base += 1024) {
        int i = base + threadIdx.x;
        int v = (i < NN) ? cnt[i] : 0;
        int x = v;
#pragma unroll
        for (int o = 1; o < 32; o <<= 1) {
            int t = __shfl_up_sync(0xffffffffu, x, o);
            if (lane >= o) x += t;
        }
        if (lane == 31) wsum[wid] = x;
        __syncthreads();
        if (wid == 0) {
            int s = wsum[lane];
#pragma unroll
            for (int o = 1; o < 32; o <<= 1) {
                int t = __shfl_up_sync(0xffffffffu, s, o);
                if (lane >= o) s += t;
            }
            wsum[lane] = s;
        }
        __syncthreads();
        int incl = x + (wid ? wsum[wid - 1] : 0) + carry;
        if (i < NN) rowptr[i + 1] = incl;
        int total = wsum[31];
        __syncthreads();
        if (threadIdx.x == 0) carry += total;
        __syncthreads();
    }
}

__global__ void k_scatter(const int* __restrict__ dst, const int* __restrict__ src,
                          const int* __restrict__ rowptr, int* cnt, int* adj) {
    int i = blockIdx.x * blockDim.x + threadIdx.x;
    if (i < EE) {
        int d = dst[i];
        int pos = rowptr[d] + (atomicAdd(&cnt[d], -1) - 1);
        adj[pos] = src[i];
    }
}

// ---------------- fused GATv2 layer (float4 head-group layout) -----------------
__device__ __forceinline__ float head_logit(float4 xv, float4 xr, float4 a) {
    float t = lrelu(xv.x + xr.x) * a.x
            + lrelu(xv.y + xr.y) * a.y
            + lrelu(xv.z + xr.z) * a.z
            + lrelu(xv.w + xr.w) * a.w;
    t += __shfl_xor_sync(0xffffffffu, t, 1);
    t += __shfl_xor_sync(0xffffffffu, t, 2);
    t += __shfl_xor_sync(0xffffffffu, t, 4);
    return t;
}

__global__ __launch_bounds__(256)
void k_aggregate(const float* __restrict__ att, const float* __restrict__ bias) {
    int node = (blockIdx.x * blockDim.x + threadIdx.x) >> 5;
    int lane = threadIdx.x & 31;
    if (node >= NN) return;

    const float* xli = g_xl + (size_t)node * NHC;
    const float* xri = g_xr + (size_t)node * NHC;
    const float4* a4 = reinterpret_cast<const float4*>(att);
    const uint64_t pl = pol_evict_last();
    const uint64_t pf = pol_evict_first();

    float4 attv[3], xrv[3], acc[3];
    float m[3], d[3];
#pragma unroll
    for (int g = 0; g < 3; g++) {
        attv[g] = a4[g * 32 + lane];
        xrv[g]  = ldg_hint4(xri + (g * 32 + lane) * 4, pf);   // streamed, read-once
    }
#pragma unroll
    for (int g = 0; g < 3; g++) {
        float4 xv = ldg_hint4(xli + (g * 32 + lane) * 4, pl); // reuse set
        m[g] = head_logit(xv, xrv[g], attv[g]);
        d[g] = 1.f;
        acc[g] = xv;
    }

    const int start = g_rowptr[node], end = g_rowptr[node + 1];
    int s_next = (start < end) ? g_adj[start] : 0;
    for (int p = start; p < end; ++p) {
        int s = s_next;
        if (p + 1 < end) s_next = g_adj[p + 1];               // break index->gather chain
        const float* xs = g_xl + (size_t)s * NHC;
#pragma unroll
        for (int g = 0; g < 3; g++) {
            float4 xv = ldg_hint4(xs + (g * 32 + lane) * 4, pl);
            float t  = head_logit(xv, xrv[g], attv[g]);
            float mn = fmaxf(m[g], t);
            float e  = __expf(fminf(m[g], t) - mn);
            bool  big = t > m[g];
            float pp = big ? e : 1.f;
            float qq = big ? 1.f : e;
            d[g] = d[g] * pp + qq;
            acc[g].x = acc[g].x * pp + qq * xv.x;
            acc[g].y = acc[g].y * pp + qq * xv.y;
            acc[g].z = acc[g].z * pp + qq * xv.z;
            acc[g].w = acc[g].w * pp + qq * xv.w;
            m[g] = mn;
        }
    }

    float4 s4 = make_float4(0.f, 0.f, 0.f, 0.f);
#pragma unroll
    for (int g = 0; g < 3; g++) {
        float dinv = 1.f / d[g];
        s4.x += acc[g].x * dinv;
        s4.y += acc[g].y * dinv;
        s4.z += acc[g].z * dinv;
        s4.w += acc[g].w * dinv;
    }
#pragma unroll
    for (int o = 8; o <= 16; o <<= 1) {
        s4.x += __shfl_xor_sync(0xffffffffu, s4.x, o);
        s4.y += __shfl_xor_sync(0xffffffffu, s4.y, o);
        s4.z += __shfl_xor_sync(0xffffffffu, s4.z, o);
        s4.w += __shfl_xor_sync(0xffffffffu, s4.w, o);
    }
    if (lane < 8) {
        float4 b = reinterpret_cast<const float4*>(bias)[lane];
        float4 o4;
        o4.x = s4.x * (1.f / NH) + b.x;
        o4.y = s4.y * (1.f / NH) + b.y;
        o4.z = s4.z * (1.f / NH) + b.z;
        o4.w = s4.w * (1.f / NH) + b.w;
        o4.x = o4.x > 0.f ? o4.x : (__expf(o4.x) - 1.f);
        o4.y = o4.y > 0.f ? o4.y : (__expf(o4.y) - 1.f);
        o4.z = o4.z > 0.f ? o4.z : (__expf(o4.z) - 1.f);
        o4.w = o4.w > 0.f ? o4.w : (__expf(o4.w) - 1.f);
        reinterpret_cast<float4*>(g_act + (size_t)node * HC)[lane] = o4;
    }
}

// ---------------- output GATv2 layer (heads=1, C=2) ----------------------------
__global__ void k_lin_out(const float* __restrict__ Wl, const float* __restrict__ bl,
                          const float* __restrict__ Wr, const float* __restrict__ br) {
    int node = (blockIdx.x * blockDim.x + threadIdx.x) >> 5;
    int lane = threadIdx.x & 31;
    if (node >= NN) return;
    float hv = g_act[(size_t)node * HC + lane];
#pragma unroll
    for (int j = 0; j < NC; j++) {
        float a = hv * Wl[lane * NC + j];
        float b = hv * Wr[lane * NC + j];
#pragma unroll
        for (int o = 16; o; o >>= 1) {
            a += __shfl_xor_sync(0xffffffffu, a, o);
            b += __shfl_xor_sync(0xffffffffu, b, o);
        }
        if (lane == 0) {
            g_xlo[node * NC + j] = a + bl[j];
            g_xro[node * NC + j] = b + br[j];
        }
    }
}

__global__ void k_out(const float* __restrict__ atto, const float* __restrict__ biaso,
                      float* __restrict__ out) {
    int node = (blockIdx.x * blockDim.x + threadIdx.x) >> 5;
    int lane = threadIdx.x & 31;
    if (node >= NN) return;
    float x0 = g_xlo[2 * node], x1 = g_xlo[2 * node + 1];
    float r0 = g_xro[2 * node], r1 = g_xro[2 * node + 1];
    float a0 = atto[0], a1 = atto[1];
    float sl = a0 * lrelu(x0 + r0) + a1 * lrelu(x1 + r1);

    float m, d, s0, s1;
    if (lane == 0) { m = sl; d = 1.f; s0 = x0; s1 = x1; }
    else           { m = -3.0e38f; d = 0.f; s0 = 0.f; s1 = 0.f; }

    const int start = g_rowptr[node], end = g_rowptr[node + 1];
    for (int p = start + lane; p < end; p += 32) {
        int s = g_adj[p];
        float y0 = g_xlo[2 * s], y1 = g_xlo[2 * s + 1];
        float l  = a0 * lrelu(y0 + r0) + a1 * lrelu(y1 + r1);
        float mn = fmaxf(m, l);
        float sc = __expf(m - mn);
        float w  = __expf(l - mn);
        d  = d * sc + w;
        s0 = s0 * sc + w * y0;
        s1 = s1 * sc + w * y1;
        m  = mn;
    }
#pragma unroll
    for (int o = 16; o; o >>= 1) {
        float m2 = __shfl_xor_sync(0xffffffffu, m, o);
        float d2 = __shfl_xor_sync(0xffffffffu, d, o);
        float t0 = __shfl_xor_sync(0xffffffffu, s0, o);
        float t1 = __shfl_xor_sync(0xffffffffu, s1, o);
        float mn  = fmaxf(m, m2);
        float sc1 = __expf(m - mn);
        float sc2 = __expf(m2 - mn);
        d  = d * sc1 + d2 * sc2;
        s0 = s0 * sc1 + t0 * sc2;
        s1 = s1 * sc1 + t1 * sc2;
        m  = mn;
    }
    if (lane == 0) {
        float dinv = 1.f / d;
        out[2 * node]     = s0 * dinv + biaso[0];
        out[2 * node + 1] = s1 * dinv + biaso[1];
    }
}

// ---------------- launch --------------------------------------------------------
extern "C" void kernel_launch(void* const* d_in, const int* in_sizes, int n_in,
                              void* d_out, int out_size) {
    const float* x     = (const float*)d_in[0];
    const int*   ei    = (const int*)d_in[1];
    const float* Wl0   = (const float*)d_in[2];
    const float* bl0   = (const float*)d_in[3];
    const float* Wr0   = (const float*)d_in[4];
    const float* br0   = (const float*)d_in[5];
    const float* att0  = (const float*)d_in[6];
    const float* bias0 = (const float*)d_in[7];
    const float* Wl1   = (const float*)d_in[8];
    const float* bl1   = (const float*)d_in[9];
    const float* Wr1   = (const float*)d_in[10];
    const float* br1   = (const float*)d_in[11];
    const float* att1  = (const float*)d_in[12];
    const float* bias1 = (const float*)d_in[13];
    const float* Wlo   = (const float*)d_in[14];
    const float* blo   = (const float*)d_in[15];
    const float* Wro   = (const float*)d_in[16];
    const float* bro   = (const float*)d_in[17];
    const float* atto  = (const float*)d_in[18];
    const float* biaso = (const float*)d_in[19];
    float* out = (float*)d_out;

    const int* src = ei;        // edge_index[0]
    const int* dst = ei + EE;   // edge_index[1]

    float *pxl, *pxr, *pact;
    int *pcnt, *prow, *padj;
    __nv_bfloat16 *pwh, *pwl;
    cudaGetSymbolAddress((void**)&pxl,  g_xl);
    cudaGetSymbolAddress((void**)&pxr,  g_xr);
    cudaGetSymbolAddress((void**)&pact, g_act);
    cudaGetSymbolAddress((void**)&pcnt, g_cnt);
    cudaGetSymbolAddress((void**)&prow, g_rowptr);
    cudaGetSymbolAddress((void**)&padj, g_adj);
    cudaGetSymbolAddress((void**)&pwh,  g_wh);
    cudaGetSymbolAddress((void**)&pwl,  g_wl);

    // dynamic SMEM: full-K hi/lo bf16 tiles
    const int st128 = 128 * 2 + 16, st32 = 32 * 2 + 16;
    const int smem128 = 2 * (128 * st128) + 2 * (64 * st128);  // 104448
    const int smem32  = 2 * (128 * st32)  + 2 * (64 * st32);   // 30720
    cudaFuncSetAttribute(k_gemm_mma<128>, cudaFuncAttributeMaxDynamicSharedMemorySize, smem128);
    cudaFuncSetAttribute(k_gemm_mma<32>,  cudaFuncAttributeMaxDynamicSharedMemorySize, smem32);

    // CSR by destination
    cudaMemsetAsync(pcnt, 0, NN * sizeof(int));
    k_count  <<<(EE + 255) / 256, 256>>>(dst, pcnt);
    k_scan   <<<1, 1024>>>(pcnt, prow);
    k_scatter<<<(EE + 255) / 256, 256>>>(dst, src, prow, pcnt, padj);

    dim3 gg(NHC / 64, (NN + 127) / 128, 1);

    // layer 0: split once; xr GEMM first, xl GEMM second (keeps xl hot in L2)
    k_cvtA<128><<<(NN * D0 / 4 + 255) / 256, 256>>>(x, NN);
    k_cvtW<128><<<(2 * NHC * 128 + 255) / 256, 256>>>(Wl0, Wr0);
    k_gemm_mma<128><<<gg, 256, smem128>>>(br0, pxr, pwh + (size_t)NHC * 128, pwl + (size_t)NHC * 128, NN, NHC);
    k_gemm_mma<128><<<gg, 256, smem128>>>(bl0, pxl, pwh, pwl, NN, NHC);
    k_aggregate<<<(NN + 7) / 8, 256>>>(att0, bias0);

    // layer 1
    k_cvtA<32><<<(NN * HC / 4 + 255) / 256, 256>>>(pact, NN);
    k_cvtW<32><<<(2 * NHC * 32 + 255) / 256, 256>>>(Wl1, Wr1);
    k_gemm_mma<32><<<gg, 256, smem32>>>(br1, pxr, pwh + (size_t)NHC * 32, pwl + (size_t)NHC * 32, NN, NHC);
    k_gemm_mma<32><<<gg, 256, smem32>>>(bl1, pxl, pwh, pwl, NN, NHC);
    k_aggregate<<<(NN + 7) / 8, 256>>>(att1, bias1);

    // output layer
    k_lin_out<<<(NN + 7) / 8, 256>>>(Wlo, blo, Wro, bro);
    k_out    <<<(NN + 7) / 8, 256>>>(atto, biaso, out);
}

// round 9
// speedup vs baseline: 1.0583x; 1.0583x over previous
#include <cuda_runtime.h>
#include <cuda_bf16.h>
#include <cstdint>

#define NN   50000
#define EE   400000
#define NH   12
#define HC   32
#define D0   128
#define NHC  (NH*HC)   // 384
#define NC   2

// ---------------- scratch (static device globals) -----------------------------
__device__ float g_xl[(size_t)NN * NHC];       // 76.8 MB (fits L2)
__device__ float g_xr[(size_t)NN * NHC];       // 76.8 MB
__device__ float g_act[(size_t)NN * HC];
__device__ float g_xlo[NN * NC];
__device__ float g_xro[NN * NC];
__device__ int   g_rowptr[NN + 1];
__device__ int   g_cnt[NN];
__device__ int   g_adj[EE];                    // src node ids grouped by dst

// pre-split bf16 operands
__device__ __nv_bfloat16 g_ah[(size_t)NN * D0];        // A hi (K=128 max)
__device__ __nv_bfloat16 g_al[(size_t)NN * D0];        // A lo
__device__ __nv_bfloat16 g_wh[2 * NHC * D0];           // W^T hi, [z][n][k]
__device__ __nv_bfloat16 g_wl[2 * NHC * D0];           // W^T lo

__device__ __forceinline__ float lrelu(float v) { return v > 0.f ? v : 0.2f * v; }

__device__ __forceinline__ uint32_t smem_u32(const void* p) {
    uint32_t a;
    asm("{ .reg .u64 t; cvta.to.shared.u64 t, %1; cvt.u32.u64 %0, t; }" : "=r"(a) : "l"(p));
    return a;
}
__device__ __forceinline__ void ldsm4(uint32_t* r, uint32_t addr) {
    asm volatile("ldmatrix.sync.aligned.m8n8.x4.shared.b16 {%0,%1,%2,%3}, [%4];"
                 : "=r"(r[0]), "=r"(r[1]), "=r"(r[2]), "=r"(r[3]) : "r"(addr));
}
__device__ __forceinline__ void mma_bf16(float* c, const uint32_t* a, uint32_t b0, uint32_t b1) {
    asm volatile(
        "mma.sync.aligned.m16n8k16.row.col.f32.bf16.bf16.f32 "
        "{%0,%1,%2,%3}, {%4,%5,%6,%7}, {%8,%9}, {%0,%1,%2,%3};"
        : "+f"(c[0]), "+f"(c[1]), "+f"(c[2]), "+f"(c[3])
        : "r"(a[0]), "r"(a[1]), "r"(a[2]), "r"(a[3]), "r"(b0), "r"(b1));
}

// ---------------- split kernels -------------------------------------------------
template <int K>
__global__ void k_cvtA(const float* __restrict__ A, int M) {
    int i = blockIdx.x * blockDim.x + threadIdx.x;       // float4 index
    if (i >= M * K / 4) return;
    float4 v = reinterpret_cast<const float4*>(A)[i];
    __nv_bfloat162 h01 = __floats2bfloat162_rn(v.x, v.y);
    __nv_bfloat162 h23 = __floats2bfloat162_rn(v.z, v.w);
    float2 f01 = __bfloat1622float2(h01);
    float2 f23 = __bfloat1622float2(h23);
    __nv_bfloat162 l01 = __floats2bfloat162_rn(v.x - f01.x, v.y - f01.y);
    __nv_bfloat162 l23 = __floats2bfloat162_rn(v.z - f23.x, v.w - f23.y);
    uint2 h = make_uint2(*reinterpret_cast<uint32_t*>(&h01), *reinterpret_cast<uint32_t*>(&h23));
    uint2 l = make_uint2(*reinterpret_cast<uint32_t*>(&l01), *reinterpret_cast<uint32_t*>(&l23));
    reinterpret_cast<uint2*>(g_ah)[i] = h;
    reinterpret_cast<uint2*>(g_al)[i] = l;
}

template <int K>
__global__ void k_cvtW(const float* __restrict__ Wa, const float* __restrict__ Wb) {
    int i = blockIdx.x * blockDim.x + threadIdx.x;       // over 2*NHC*K
    if (i >= 2 * NHC * K) return;
    int z = i / (NHC * K);
    int r = i % (NHC * K);
    int n = r / K, k = r % K;
    const float* W = z ? Wb : Wa;
    float v = W[(size_t)k * NHC + n];
    __nv_bfloat16 h = __float2bfloat16(v);
    __nv_bfloat16 l = __float2bfloat16(v - __bfloat162float(h));
    g_wh[(size_t)z * NHC * K + (size_t)n * K + k] = h;
    g_wl[(size_t)z * NHC * K + (size_t)n * K + k] = l;
}

// ---------------- bf16x3 HMMA GEMM: C[M,384] = A[M,K] @ W[K,384] + bias --------
// Pre-split bf16 inputs. BM=128, BN=64. blockIdx.z picks weight set / output.
template <int K>
__global__ __launch_bounds__(256, 2)
void k_gemm_mma(const float* __restrict__ ba, float* __restrict__ Ca,
                const float* __restrict__ bb_, float* __restrict__ Cb,
                int M, int Ncol) {
    constexpr int BM = 128, BN = 64;
    constexpr int ST  = K * 2 + 16;
    constexpr int SZA = BM * ST;
    constexpr int SZB = BN * ST;
    constexpr int KV  = K / 8;

    extern __shared__ char smem[];
    char* sAh = smem;
    char* sAl = smem + SZA;
    char* sBh = smem + 2 * SZA;
    char* sBl = smem + 2 * SZA + SZB;

    const float* bias = blockIdx.z ? bb_ : ba;
    float*       C    = blockIdx.z ? Cb  : Ca;
    const __nv_bfloat16* wh = g_wh + (size_t)blockIdx.z * NHC * K;
    const __nv_bfloat16* wl = g_wl + (size_t)blockIdx.z * NHC * K;

    const int rowBase = blockIdx.y * BM;
    const int colBase = blockIdx.x * BN;
    const int tid  = threadIdx.x;
    const int wid  = tid >> 5;
    const int lane = tid & 31;
    const int wm   = wid & 3;
    const int wn   = wid >> 2;

    for (int i = tid; i < BM * KV; i += 256) {
        int r  = i / KV;
        int c  = i % KV;
        int gr = rowBase + r;
        uint4 h = make_uint4(0, 0, 0, 0), l = make_uint4(0, 0, 0, 0);
        if (gr < M) {
            h = reinterpret_cast<const uint4*>(g_ah + (size_t)gr * K)[c];
            l = reinterpret_cast<const uint4*>(g_al + (size_t)gr * K)[c];
        }
        *reinterpret_cast<uint4*>(sAh + r * ST + c * 16) = h;
        *reinterpret_cast<uint4*>(sAl + r * ST + c * 16) = l;
    }
    for (int i = tid; i < BN * KV; i += 256) {
        int n = i / KV;
        int c = i % KV;
        *reinterpret_cast<uint4*>(sBh + n * ST + c * 16) =
            reinterpret_cast<const uint4*>(wh + (size_t)(colBase + n) * K)[c];
        *reinterpret_cast<uint4*>(sBl + n * ST + c * 16) =
            reinterpret_cast<const uint4*>(wl + (size_t)(colBase + n) * K)[c];
    }
    __syncthreads();

    const uint32_t sb = smem_u32(smem);
    const int g  = lane >> 3;
    const int ri = lane & 7;

    float acc[2][4][4];
#pragma unroll
    for (int mt = 0; mt < 2; mt++)
#pragma unroll
        for (int nt = 0; nt < 4; nt++)
#pragma unroll
            for (int q = 0; q < 4; q++) acc[mt][nt][q] = 0.f;

#pragma unroll
    for (int kk = 0; kk < K / 16; kk++) {
        uint32_t aH[2][4], aL[2][4], bH[2][4], bL[2][4];
#pragma unroll
        for (int mt = 0; mt < 2; mt++) {
            int row = wm * 32 + mt * 16 + ri + (g & 1) * 8;
            int col = kk * 16 + (g >> 1) * 8;
            uint32_t ad = sb + row * ST + col * 2;
            ldsm4(aH[mt], ad);
            ldsm4(aL[mt], ad + SZA);
        }
#pragma unroll
        for (int p = 0; p < 2; p++) {
            int row = wn * 32 + p * 16 + ri + (g >> 1) * 8;
            int col = kk * 16 + (g & 1) * 8;
            uint32_t bd = sb + 2 * SZA + row * ST + col * 2;
            ldsm4(bH[p], bd);
            ldsm4(bL[p], bd + SZB);
        }
#pragma unroll
        for (int mt = 0; mt < 2; mt++)
#pragma unroll
            for (int nt = 0; nt < 4; nt++) {
                int p = nt >> 1, o = (nt & 1) * 2;
                mma_bf16(acc[mt][nt], aH[mt], bH[p][o], bH[p][o + 1]);
                mma_bf16(acc[mt][nt], aH[mt], bL[p][o], bL[p][o + 1]);
                mma_bf16(acc[mt][nt], aL[mt], bH[p][o], bH[p][o + 1]);
            }
    }

#pragma unroll
    for (int mt = 0; mt < 2; mt++) {
#pragma unroll
        for (int nt = 0; nt < 4; nt++) {
            int gr = rowBase + wm * 32 + mt * 16 + (lane >> 2);
            int gc = colBase + wn * 32 + nt * 8 + (lane & 3) * 2;
            float b0 = bias[gc], b1 = bias[gc + 1];
            if (gr < M) {
                float2 o = make_float2(acc[mt][nt][0] + b0, acc[mt][nt][1] + b1);
                *reinterpret_cast<float2*>(&C[(size_t)gr * Ncol + gc]) = o;
            }
            if (gr + 8 < M) {
                float2 o = make_float2(acc[mt][nt][2] + b0, acc[mt][nt][3] + b1);
                *reinterpret_cast<float2*>(&C[(size_t)(gr + 8) * Ncol + gc]) = o;
            }
        }
    }
}

// ---------------- CSR build ----------------------------------------------------
__global__ void k_count(const int* __restrict__ dst, int* cnt) {
    int i = blockIdx.x * blockDim.x + threadIdx.x;
    if (i < EE) atomicAdd(&cnt[dst[i]], 1);
}

__global__ void k_scan(const int* __restrict__ cnt, int* __restrict__ rowptr) {
    __shared__ int wsum[32];
    __shared__ int carry;
    int lane = threadIdx.x & 31, wid = threadIdx.x >> 5;
    if (threadIdx.x == 0) { carry = 0; rowptr[0] = 0; }
    __syncthreads();
    for (int base = 0; base < NN; base += 1024) {
        int i = base + threadIdx.x;
        int v = (i < NN) ? cnt[i] : 0;
        int x = v;
#pragma unroll
        for (int o = 1; o < 32; o <<= 1) {
            int t = __shfl_up_sync(0xffffffffu, x, o);
            if (lane >= o) x += t;
        }
        if (lane == 31) wsum[wid] = x;
        __syncthreads();
        if (wid == 0) {
            int s = wsum[lane];
#pragma unroll
            for (int o = 1; o < 32; o <<= 1) {
                int t = __shfl_up_sync(0xffffffffu, s, o);
                if (lane >= o) s += t;
            }
            wsum[lane] = s;
        }
        __syncthreads();
        int incl = x + (wid ? wsum[wid - 1] : 0) + carry;
        if (i < NN) rowptr[i + 1] = incl;
        int total = wsum[31];
        __syncthreads();
        if (threadIdx.x == 0) carry += total;
        __syncthreads();
    }
}

__global__ void k_scatter(const int* __restrict__ dst, const int* __restrict__ src,
                          const int* __restrict__ rowptr, int* cnt, int* adj) {
    int i = blockIdx.x * blockDim.x + threadIdx.x;
    if (i < EE) {
        int d = dst[i];
        int pos = rowptr[d] + (atomicAdd(&cnt[d], -1) - 1);
        adj[pos] = src[i];
    }
}

// ---------------- fused GATv2 layer --------------------------------------------
// Softmax anchored at the self-loop logit (constant per node; exp cannot
// overflow for these magnitudes). No fmax chain; edges unrolled x2 with
// independent accumulators -> 6 gathers in flight per warp.
__device__ __forceinline__ float head_logit(float4 xv, float4 xr, float4 a) {
    float t = lrelu(xv.x + xr.x) * a.x
            + lrelu(xv.y + xr.y) * a.y
            + lrelu(xv.z + xr.z) * a.z
            + lrelu(xv.w + xr.w) * a.w;
    t += __shfl_xor_sync(0xffffffffu, t, 1);
    t += __shfl_xor_sync(0xffffffffu, t, 2);
    t += __shfl_xor_sync(0xffffffffu, t, 4);
    return t;
}

__global__ __launch_bounds__(256)
void k_aggregate(const float* __restrict__ att, const float* __restrict__ bias) {
    int node = (blockIdx.x * blockDim.x + threadIdx.x) >> 5;
    int lane = threadIdx.x & 31;
    if (node >= NN) return;

    const float4* xli = reinterpret_cast<const float4*>(g_xl + (size_t)node * NHC);
    const float4* xri = reinterpret_cast<const float4*>(g_xr + (size_t)node * NHC);
    const float4* a4  = reinterpret_cast<const float4*>(att);

    float4 attv[3], xrv[3];
#pragma unroll
    for (int g = 0; g < 3; g++) {
        attv[g] = a4[g * 32 + lane];
        xrv[g]  = xri[g * 32 + lane];
    }

    // anchor m = self logit; self contributes e=1
    float m[3], d0[3], d1[3];
    float4 acc0[3], acc1[3];
#pragma unroll
    for (int g = 0; g < 3; g++) {
        float4 xv = xli[g * 32 + lane];
        m[g]  = head_logit(xv, xrv[g], attv[g]);
        d0[g] = 1.f;  d1[g] = 0.f;
        acc0[g] = xv;
        acc1[g] = make_float4(0.f, 0.f, 0.f, 0.f);
    }

    const int start = g_rowptr[node], end = g_rowptr[node + 1];
    int p = start;
    for (; p + 1 < end; p += 2) {
        int sa = g_adj[p];
        int sb = g_adj[p + 1];
        const float4* xsa = reinterpret_cast<const float4*>(g_xl + (size_t)sa * NHC);
        const float4* xsb = reinterpret_cast<const float4*>(g_xl + (size_t)sb * NHC);
        float4 xva[3], xvb[3];
#pragma unroll
        for (int g = 0; g < 3; g++) {
            xva[g] = xsa[g * 32 + lane];
            xvb[g] = xsb[g * 32 + lane];
        }
#pragma unroll
        for (int g = 0; g < 3; g++) {
            float ta = head_logit(xva[g], xrv[g], attv[g]);
            float tb = head_logit(xvb[g], xrv[g], attv[g]);
            float ea = __expf(ta - m[g]);
            float eb = __expf(tb - m[g]);
            d0[g] += ea;
            d1[g] += eb;
            acc0[g].x += ea * xva[g].x;  acc1[g].x += eb * xvb[g].x;
            acc0[g].y += ea * xva[g].y;  acc1[g].y += eb * xvb[g].y;
            acc0[g].z += ea * xva[g].z;  acc1[g].z += eb * xvb[g].z;
            acc0[g].w += ea * xva[g].w;  acc1[g].w += eb * xvb[g].w;
        }
    }
    if (p < end) {
        int sa = g_adj[p];
        const float4* xsa = reinterpret_cast<const float4*>(g_xl + (size_t)sa * NHC);
#pragma unroll
        for (int g = 0; g < 3; g++) {
            float4 xva = xsa[g * 32 + lane];
            float ta = head_logit(xva, xrv[g], attv[g]);
            float ea = __expf(ta - m[g]);
            d0[g] += ea;
            acc0[g].x += ea * xva.x;
            acc0[g].y += ea * xva.y;
            acc0[g].z += ea * xva.z;
            acc0[g].w += ea * xva.w;
        }
    }

    float4 s4 = make_float4(0.f, 0.f, 0.f, 0.f);
#pragma unroll
    for (int g = 0; g < 3; g++) {
        float dinv = 1.f / (d0[g] + d1[g]);
        s4.x += (acc0[g].x + acc1[g].x) * dinv;
        s4.y += (acc0[g].y + acc1[g].y) * dinv;
        s4.z += (acc0[g].z + acc1[g].z) * dinv;
        s4.w += (acc0[g].w + acc1[g].w) * dinv;
    }
#pragma unroll
    for (int o = 8; o <= 16; o <<= 1) {
        s4.x += __shfl_xor_sync(0xffffffffu, s4.x, o);
        s4.y += __shfl_xor_sync(0xffffffffu, s4.y, o);
        s4.z += __shfl_xor_sync(0xffffffffu, s4.z, o);
        s4.w += __shfl_xor_sync(0xffffffffu, s4.w, o);
    }
    if (lane < 8) {
        float4 b = reinterpret_cast<const float4*>(bias)[lane];
        float4 o4;
        o4.x = s4.x * (1.f / NH) + b.x;
        o4.y = s4.y * (1.f / NH) + b.y;
        o4.z = s4.z * (1.f / NH) + b.z;
        o4.w = s4.w * (1.f / NH) + b.w;
        o4.x = o4.x > 0.f ? o4.x : (__expf(o4.x) - 1.f);
        o4.y = o4.y > 0.f ? o4.y : (__expf(o4.y) - 1.f);
        o4.z = o4.z > 0.f ? o4.z : (__expf(o4.z) - 1.f);
        o4.w = o4.w > 0.f ? o4.w : (__expf(o4.w) - 1.f);
        reinterpret_cast<float4*>(g_act + (size_t)node * HC)[lane] = o4;
    }
}

// ---------------- output GATv2 layer (heads=1, C=2) ----------------------------
__global__ void k_lin_out(const float* __restrict__ Wl, const float* __restrict__ bl,
                          const float* __restrict__ Wr, const float* __restrict__ br) {
    int node = (blockIdx.x * blockDim.x + threadIdx.x) >> 5;
    int lane = threadIdx.x & 31;
    if (node >= NN) return;
    float hv = g_act[(size_t)node * HC + lane];
#pragma unroll
    for (int j = 0; j < NC; j++) {
        float a = hv * Wl[lane * NC + j];
        float b = hv * Wr[lane * NC + j];
#pragma unroll
        for (int o = 16; o; o >>= 1) {
            a += __shfl_xor_sync(0xffffffffu, a, o);
            b += __shfl_xor_sync(0xffffffffu, b, o);
        }
        if (lane == 0) {
            g_xlo[node * NC + j] = a + bl[j];
            g_xro[node * NC + j] = b + br[j];
        }
    }
}

__global__ void k_out(const float* __restrict__ atto, const float* __restrict__ biaso,
                      float* __restrict__ out) {
    int node = (blockIdx.x * blockDim.x + threadIdx.x) >> 5;
    int lane = threadIdx.x & 31;
    if (node >= NN) return;
    float x0 = g_xlo[2 * node], x1 = g_xlo[2 * node + 1];
    float r0 = g_xro[2 * node], r1 = g_xro[2 * node + 1];
    float a0 = atto[0], a1 = atto[1];
    float sl = a0 * lrelu(x0 + r0) + a1 * lrelu(x1 + r1);

    // anchor at self logit (lane-parallel plain-exp accumulation)
    float d = (lane == 0) ? 1.f : 0.f;
    float s0 = (lane == 0) ? x0 : 0.f;
    float s1 = (lane == 0) ? x1 : 0.f;

    const int start = g_rowptr[node], end = g_rowptr[node + 1];
    for (int p = start + lane; p < end; p += 32) {
        int s = g_adj[p];
        float y0 = g_xlo[2 * s], y1 = g_xlo[2 * s + 1];
        float l  = a0 * lrelu(y0 + r0) + a1 * lrelu(y1 + r1);
        float w  = __expf(l - sl);
        d  += w;
        s0 += w * y0;
        s1 += w * y1;
    }
#pragma unroll
    for (int o = 16; o; o >>= 1) {
        d  += __shfl_xor_sync(0xffffffffu, d, o);
        s0 += __shfl_xor_sync(0xffffffffu, s0, o);
        s1 += __shfl_xor_sync(0xffffffffu, s1, o);
    }
    if (lane == 0) {
        float dinv = 1.f / d;
        out[2 * node]     = s0 * dinv + biaso[0];
        out[2 * node + 1] = s1 * dinv + biaso[1];
    }
}

// ---------------- launch --------------------------------------------------------
extern "C" void kernel_launch(void* const* d_in, const int* in_sizes, int n_in,
                              void* d_out, int out_size) {
    const float* x     = (const float*)d_in[0];
    const int*   ei    = (const int*)d_in[1];
    const float* Wl0   = (const float*)d_in[2];
    const float* bl0   = (const float*)d_in[3];
    const float* Wr0   = (const float*)d_in[4];
    const float* br0   = (const float*)d_in[5];
    const float* att0  = (const float*)d_in[6];
    const float* bias0 = (const float*)d_in[7];
    const float* Wl1   = (const float*)d_in[8];
    const float* bl1   = (const float*)d_in[9];
    const float* Wr1   = (const float*)d_in[10];
    const float* br1   = (const float*)d_in[11];
    const float* att1  = (const float*)d_in[12];
    const float* bias1 = (const float*)d_in[13];
    const float* Wlo   = (const float*)d_in[14];
    const float* blo   = (const float*)d_in[15];
    const float* Wro   = (const float*)d_in[16];
    const float* bro   = (const float*)d_in[17];
    const float* atto  = (const float*)d_in[18];
    const float* biaso = (const float*)d_in[19];
    float* out = (float*)d_out;

    const int* src = ei;        // edge_index[0]
    const int* dst = ei + EE;   // edge_index[1]

    float *pxl, *pxr, *pact;
    int *pcnt, *prow, *padj;
    cudaGetSymbolAddress((void**)&pxl,  g_xl);
    cudaGetSymbolAddress((void**)&pxr,  g_xr);
    cudaGetSymbolAddress((void**)&pact, g_act);
    cudaGetSymbolAddress((void**)&pcnt, g_cnt);
    cudaGetSymbolAddress((void**)&prow, g_rowptr);
    cudaGetSymbolAddress((void**)&padj, g_adj);

    // dynamic SMEM: full-K hi/lo bf16 tiles
    const int st128 = 128 * 2 + 16, st32 = 32 * 2 + 16;
    const int smem128 = 2 * (128 * st128) + 2 * (64 * st128);  // 104448
    const int smem32  = 2 * (128 * st32)  + 2 * (64 * st32);   // 30720
    cudaFuncSetAttribute(k_gemm_mma<128>, cudaFuncAttributeMaxDynamicSharedMemorySize, smem128);
    cudaFuncSetAttribute(k_gemm_mma<32>,  cudaFuncAttributeMaxDynamicSharedMemorySize, smem32);

    // CSR by destination
    cudaMemsetAsync(pcnt, 0, NN * sizeof(int));
    k_count  <<<(EE + 255) / 256, 256>>>(dst, pcnt);
    k_scan   <<<1, 1024>>>(pcnt, prow);
    k_scatter<<<(EE + 255) / 256, 256>>>(dst, src, prow, pcnt, padj);

    dim3 gg(NHC / 64, (NN + 127) / 128, 2);

    // layer 0
    k_cvtA<128><<<(NN * D0 / 4 + 255) / 256, 256>>>(x, NN);
    k_cvtW<128><<<(2 * NHC * 128 + 255) / 256, 256>>>(Wl0, Wr0);
    k_gemm_mma<128><<<gg, 256, smem128>>>(bl0, pxl, br0, pxr, NN, NHC);
    k_aggregate<<<(NN + 7) / 8, 256>>>(att0, bias0);

    // layer 1
    k_cvtA<32><<<(NN * HC / 4 + 255) / 256, 256>>>(pact, NN);
    k_cvtW<32><<<(2 * NHC * 32 + 255) / 256, 256>>>(Wl1, Wr1);
    k_gemm_mma<32><<<gg, 256, smem32>>>(bl1, pxl, br1, pxr, NN, NHC);
    k_aggregate<<<(NN + 7) / 8, 256>>>(att1, bias1);

    // output layer
    k_lin_out<<<(NN + 7) / 8, 256>>>(Wlo, blo, Wro, bro);
    k_out    <<<(NN + 7) / 8, 256>>>(atto, biaso, out);
}